// round 4
// baseline (speedup 1.0000x reference)
#include <cuda_runtime.h>
#include <math.h>

// FFM forward: B=16384, LATENT=16, F=6 fields.
// DIMS     = {1000000, 500000, 500000, 100000, 10000, 1000}
// SEQ_LENS = {1, 1, 50, 20, 1, 1}
//
// Layout this round: 1 thread = (slot, lane) of one batch element.
// blockDim = 160 = 16 lanes x 5 slots x 2 elements  -> only 6 accumulators
// per thread (low regs, high occupancy), tokens staged in smem so every
// embedding gather is an independent LDG (high MLP).

#define B_TOTAL 16384
#define LAT 16

__global__ __launch_bounds__(160) void ffm_kernel(
    const int* __restrict__ x0, const int* __restrict__ x1, const int* __restrict__ x2,
    const int* __restrict__ x3, const int* __restrict__ x4, const int* __restrict__ x5,
    const float* __restrict__ E0, const float* __restrict__ E1, const float* __restrict__ E2,
    const float* __restrict__ E3, const float* __restrict__ E4, const float* __restrict__ E5,
    const float* __restrict__ L0, const float* __restrict__ L1, const float* __restrict__ L2,
    const float* __restrict__ L3, const float* __restrict__ L4, const float* __restrict__ L5,
    const float* __restrict__ Wd, const float* __restrict__ bd,
    float* __restrict__ out)
{
    __shared__ int   tk[2][74];          // staged tokens: [elem][f0|f1|f2*50|f3*20|f4|f5]
    __shared__ float sm[2][6][5][16];    // per-field per-slot means, per lane

    const int tid = threadIdx.x;
    const int bb  = blockIdx.x * 2;

    // ---- stage all tokens for the 2 elements of this block ----
    if (tid < 148) {
        const int e = tid / 74, o = tid % 74;
        const int b = bb + e;
        int v;
        if      (o == 0)  v = x0[b];
        else if (o == 1)  v = x1[b];
        else if (o < 52)  v = x2[(size_t)b * 50 + (o - 2)];
        else if (o < 72)  v = x3[(size_t)b * 20 + (o - 52)];
        else if (o == 72) v = x4[b];
        else              v = x5[b];
        tk[e][o] = v;
    }
    __syncthreads();

    const int lane = tid & 15;
    const int sy   = (tid >> 4) % 5;     // slot index for this thread
    const int z    = tid / 80;           // which of the 2 elements
    const int b    = bb + z;

    // Wd broadcast (mean scaling folded in)
    const float w0 = __ldg(Wd + 0);
    const float w1 = __ldg(Wd + 1);
    const float w2 = __ldg(Wd + 2) * (1.0f / 50.0f);
    const float w3 = __ldg(Wd + 3) * (1.0f / 20.0f);
    const float w4 = __ldg(Wd + 4);
    const float w5 = __ldg(Wd + 5);

    float lin = 0.f;
    float a0, a1, a2, a3, a4, a5;

    // ---- field 0 (seq=1) ----
    {
        const int tok = tk[z][0];
        a0  = __ldg(E0 + ((size_t)sy * 1000000 + tok) * LAT + lane);
        lin += __ldg(L0 + tok) * w0;
    }
    // ---- field 1 (seq=1) ----
    {
        const int tok = tk[z][1];
        a1  = __ldg(E1 + ((size_t)sy * 500000 + tok) * LAT + lane);
        lin += __ldg(L1 + tok) * w1;
    }
    // ---- field 2 (seq=50): fully unrolled, 4 partial accumulators ----
    {
        const float* base = E2 + (size_t)sy * 500000 * LAT + lane;
        float p[4] = {0.f, 0.f, 0.f, 0.f};
#pragma unroll
        for (int t = 0; t < 50; ++t) {
            const int tok = tk[z][2 + t];
            p[t & 3] += __ldg(base + (size_t)tok * LAT);
            lin      += __ldg(L2 + tok) * w2;
        }
        a2 = (p[0] + p[1] + p[2] + p[3]) * (1.0f / 50.0f);
    }
    // ---- field 3 (seq=20): fully unrolled, 4 partial accumulators ----
    {
        const float* base = E3 + (size_t)sy * 100000 * LAT + lane;
        float p[4] = {0.f, 0.f, 0.f, 0.f};
#pragma unroll
        for (int t = 0; t < 20; ++t) {
            const int tok = tk[z][52 + t];
            p[t & 3] += __ldg(base + (size_t)tok * LAT);
            lin      += __ldg(L3 + tok) * w3;
        }
        a3 = (p[0] + p[1] + p[2] + p[3]) * (1.0f / 20.0f);
    }
    // ---- field 4 (seq=1) ----
    {
        const int tok = tk[z][72];
        a4  = __ldg(E4 + ((size_t)sy * 10000 + tok) * LAT + lane);
        lin += __ldg(L4 + tok) * w4;
    }
    // ---- field 5 (seq=1) ----
    {
        const int tok = tk[z][73];
        a5  = __ldg(E5 + ((size_t)sy * 1000 + tok) * LAT + lane);
        lin += __ldg(L5 + tok) * w5;
    }

    // ---- exchange slot means through smem ----
    sm[z][0][sy][lane] = a0;
    sm[z][1][sy][lane] = a1;
    sm[z][2][sy][lane] = a2;
    sm[z][3][sy][lane] = a3;
    sm[z][4][sy][lane] = a4;
    sm[z][5][sy][lane] = a5;
    __syncthreads();

    // ---- fm = sum over pairs (i<j): a_i[slot j-1] . a_j[slot i] ----
    // computed redundantly by all threads (keeps full warps for shfl)
    float fm = 0.f;
    fm += sm[z][0][0][lane] * sm[z][1][0][lane];  // (0,1)
    fm += sm[z][0][1][lane] * sm[z][2][0][lane];  // (0,2)
    fm += sm[z][0][2][lane] * sm[z][3][0][lane];  // (0,3)
    fm += sm[z][0][3][lane] * sm[z][4][0][lane];  // (0,4)
    fm += sm[z][0][4][lane] * sm[z][5][0][lane];  // (0,5)
    fm += sm[z][1][1][lane] * sm[z][2][1][lane];  // (1,2)
    fm += sm[z][1][2][lane] * sm[z][3][1][lane];  // (1,3)
    fm += sm[z][1][3][lane] * sm[z][4][1][lane];  // (1,4)
    fm += sm[z][1][4][lane] * sm[z][5][1][lane];  // (1,5)
    fm += sm[z][2][2][lane] * sm[z][3][2][lane];  // (2,3)
    fm += sm[z][2][3][lane] * sm[z][4][2][lane];  // (2,4)
    fm += sm[z][2][4][lane] * sm[z][5][2][lane];  // (2,5)
    fm += sm[z][3][3][lane] * sm[z][4][3][lane];  // (3,4)
    fm += sm[z][3][4][lane] * sm[z][5][3][lane];  // (3,5)
    fm += sm[z][4][4][lane] * sm[z][5][4][lane];  // (4,5)

    // reduce over the 16 latent lanes (all 32 lanes of every warp active)
    fm += __shfl_xor_sync(0xffffffffu, fm, 8, 16);
    fm += __shfl_xor_sync(0xffffffffu, fm, 4, 16);
    fm += __shfl_xor_sync(0xffffffffu, fm, 2, 16);
    fm += __shfl_xor_sync(0xffffffffu, fm, 1, 16);

    if (sy == 0 && lane == 0) {
        float v = lin + __ldg(bd);
        v = v > 0.f ? v : 0.f;      // relu
        v += fm;
        out[b] = 1.0f / (1.0f + expf(-v));
    }
}

extern "C" void kernel_launch(void* const* d_in, const int* in_sizes, int n_in,
                              void* d_out, int out_size)
{
    static const long DIMS[6] = {1000000, 500000, 500000, 100000, 10000, 1000};

    const int*   x[6];
    const float* E[6];
    const float* L[6];

    for (int i = 0; i < 6; ++i) x[i] = (const int*)d_in[i];

    // Inputs 6..17 are E and L tables in field order; disambiguate by size:
    // E_i has 80*DIMS[i] elements, L_i has DIMS[i]. Disjoint sets.
    int ei = 0, li = 0;
    for (int i = 6; i < 18 && i < n_in; ++i) {
        long sz = (long)in_sizes[i];
        if (ei < 6 && sz == 80L * DIMS[ei]) {
            E[ei++] = (const float*)d_in[i];
        } else {
            L[li++] = (const float*)d_in[i];
        }
    }

    const float* Wd = (const float*)d_in[18];
    const float* bd = (const float*)d_in[19];

    const int threads = 160;                 // 16 lanes x 5 slots x 2 elements
    const int blocks  = B_TOTAL / 2;         // 8192 blocks

    ffm_kernel<<<blocks, threads>>>(
        x[0], x[1], x[2], x[3], x[4], x[5],
        E[0], E[1], E[2], E[3], E[4], E[5],
        L[0], L[1], L[2], L[3], L[4], L[5],
        Wd, bd, (float*)d_out);
}

// round 5
// speedup vs baseline: 1.0847x; 1.0847x over previous
#include <cuda_runtime.h>
#include <math.h>

// FFM forward: B=16384, LATENT=16, F=6 fields.
// DIMS     = {1000000, 500000, 500000, 100000, 10000, 1000}
// SEQ_LENS = {1, 1, 50, 20, 1, 1}
//
// Round 4: L2 phasing. Heavy multi-token fields (2: seq=50, 3: seq=20) are
// done in dedicated kernels whose working set is L2-focused (E3 = 32MB fits
// entirely in the 126MB L2; E2 unique rows ~129MB ~ L2 size). Their 5-slot
// mean vectors go to __device__ scratch. A final kernel does the cheap
// fields, L gathers (once per 16-lane group, not 5x), and the epilogue.

#define B_TOTAL 16384
#define LAT 16

__device__ float g_M2[(size_t)B_TOTAL * 5 * LAT];   // 5.24 MB
__device__ float g_M3[(size_t)B_TOTAL * 5 * LAT];   // 5.24 MB

// ---------------------------------------------------------------------------
// Phase kernel: compute 5-slot mean embeddings for one multi-token field.
// Thread = (slot, lane); BPB batch elements per block; tokens staged in smem.
// ---------------------------------------------------------------------------
template<int SEQ, int DIM, int WHICH>
__global__ __launch_bounds__(320) void mean_kernel(const int* __restrict__ x,
                                                   const float* __restrict__ E)
{
    constexpr int BPB = 4;                       // 320 threads = 80 * 4
    __shared__ int tk[BPB][SEQ];

    const int tid = threadIdx.x;
    const int b0  = blockIdx.x * BPB;

    for (int i = tid; i < BPB * SEQ; i += 320) {
        const int e = i / SEQ, t = i % SEQ;
        tk[e][t] = x[(size_t)(b0 + e) * SEQ + t];
    }
    __syncthreads();

    const int lane = tid & 15;
    const int sy   = (tid >> 4) % 5;
    const int z    = tid / 80;

    const float* base = E + (size_t)sy * DIM * LAT + lane;

    float p[4] = {0.f, 0.f, 0.f, 0.f};
#pragma unroll
    for (int t = 0; t < SEQ; ++t) {
        p[t & 3] += __ldg(base + (size_t)tk[z][t] * LAT);
    }
    const float m = (p[0] + p[1] + p[2] + p[3]) * (1.0f / (float)SEQ);

    float* M = (WHICH == 2) ? g_M2 : g_M3;
    M[((size_t)(b0 + z) * 5 + sy) * LAT + lane] = m;   // 64B coalesced per (z,sy)
}

// ---------------------------------------------------------------------------
// Final kernel: fields 0,1,4,5 gathers + all L gathers + fm/lin epilogue.
// 16 lanes per batch element (lane = latent dim), 256 threads = 16 elements.
// ---------------------------------------------------------------------------
__global__ __launch_bounds__(256) void final_kernel(
    const int* __restrict__ x0, const int* __restrict__ x1, const int* __restrict__ x2,
    const int* __restrict__ x3, const int* __restrict__ x4, const int* __restrict__ x5,
    const float* __restrict__ E0, const float* __restrict__ E1,
    const float* __restrict__ E4, const float* __restrict__ E5,
    const float* __restrict__ L0, const float* __restrict__ L1, const float* __restrict__ L2,
    const float* __restrict__ L3, const float* __restrict__ L4, const float* __restrict__ L5,
    const float* __restrict__ Wd, const float* __restrict__ bd,
    float* __restrict__ out)
{
    __shared__ int tk[16][74];   // [elem][f0|f1|f2*50|f3*20|f4|f5]

    const int tid = threadIdx.x;
    const int b0  = blockIdx.x * 16;

    for (int i = tid; i < 16 * 74; i += 256) {
        const int e = i / 74, o = i % 74;
        const int b = b0 + e;
        int v;
        if      (o == 0)  v = x0[b];
        else if (o == 1)  v = x1[b];
        else if (o < 52)  v = x2[(size_t)b * 50 + (o - 2)];
        else if (o < 72)  v = x3[(size_t)b * 20 + (o - 52)];
        else if (o == 72) v = x4[b];
        else              v = x5[b];
        tk[e][o] = v;
    }
    __syncthreads();

    const int lane = tid & 15;
    const int z    = tid >> 4;
    const int b    = b0 + z;

    const float w0 = __ldg(Wd + 0);
    const float w1 = __ldg(Wd + 1);
    const float w2 = __ldg(Wd + 2) * (1.0f / 50.0f);
    const float w3 = __ldg(Wd + 3) * (1.0f / 20.0f);
    const float w4 = __ldg(Wd + 4);
    const float w5 = __ldg(Wd + 5);

    // single-token field rows (5 slots each, independent 64B-coalesced loads)
    const int t0 = tk[z][0], t1 = tk[z][1], t4 = tk[z][72], t5 = tk[z][73];
    float a0[5], a1[5], a4[5], a5[5], m2[5], m3[5];
#pragma unroll
    for (int s = 0; s < 5; ++s) {
        a0[s] = __ldg(E0 + ((size_t)s * 1000000 + t0) * LAT + lane);
        a1[s] = __ldg(E1 + ((size_t)s *  500000 + t1) * LAT + lane);
        a4[s] = __ldg(E4 + ((size_t)s *   10000 + t4) * LAT + lane);
        a5[s] = __ldg(E5 + ((size_t)s *    1000 + t5) * LAT + lane);
        m2[s] = g_M2[((size_t)b * 5 + s) * LAT + lane];
        m3[s] = g_M3[((size_t)b * 5 + s) * LAT + lane];
    }

    // linear term: L gathers once per 16-lane group (broadcast within warp)
    float lp[4];
    lp[0] = __ldg(L0 + t0) * w0;
    lp[1] = __ldg(L1 + t1) * w1;
    lp[2] = __ldg(L4 + t4) * w4;
    lp[3] = __ldg(L5 + t5) * w5;
#pragma unroll
    for (int t = 0; t < 50; ++t) lp[t & 3] += __ldg(L2 + tk[z][2 + t]) * w2;
#pragma unroll
    for (int t = 0; t < 20; ++t) lp[t & 3] += __ldg(L3 + tk[z][52 + t]) * w3;
    const float lin = (lp[0] + lp[1]) + (lp[2] + lp[3]);

    // fm = sum over pairs (i<j): a_i[slot j-1] * a_j[slot i]
    float fm = 0.f;
    fm += a0[0]*a1[0];   // (0,1)
    fm += a0[1]*m2[0];   // (0,2)
    fm += a0[2]*m3[0];   // (0,3)
    fm += a0[3]*a4[0];   // (0,4)
    fm += a0[4]*a5[0];   // (0,5)
    fm += a1[1]*m2[1];   // (1,2)
    fm += a1[2]*m3[1];   // (1,3)
    fm += a1[3]*a4[1];   // (1,4)
    fm += a1[4]*a5[1];   // (1,5)
    fm += m2[2]*m3[2];   // (2,3)
    fm += m2[3]*a4[2];   // (2,4)
    fm += m2[4]*a5[2];   // (2,5)
    fm += m3[3]*a4[3];   // (3,4)
    fm += m3[4]*a5[3];   // (3,5)
    fm += a4[4]*a5[4];   // (4,5)

    // reduce fm over the 16 latent lanes
    fm += __shfl_xor_sync(0xffffffffu, fm, 8, 16);
    fm += __shfl_xor_sync(0xffffffffu, fm, 4, 16);
    fm += __shfl_xor_sync(0xffffffffu, fm, 2, 16);
    fm += __shfl_xor_sync(0xffffffffu, fm, 1, 16);

    if (lane == 0) {
        float v = lin + __ldg(bd);
        v = v > 0.f ? v : 0.f;      // relu
        v += fm;
        out[b] = 1.0f / (1.0f + expf(-v));
    }
}

extern "C" void kernel_launch(void* const* d_in, const int* in_sizes, int n_in,
                              void* d_out, int out_size)
{
    static const long DIMS[6] = {1000000, 500000, 500000, 100000, 10000, 1000};

    const int*   x[6];
    const float* E[6];
    const float* L[6];

    for (int i = 0; i < 6; ++i) x[i] = (const int*)d_in[i];

    // Inputs 6..17 are E and L tables in field order; disambiguate by size:
    // E_i has 80*DIMS[i] elements, L_i has DIMS[i]. Disjoint sets.
    int ei = 0, li = 0;
    for (int i = 6; i < 18 && i < n_in; ++i) {
        long sz = (long)in_sizes[i];
        if (ei < 6 && sz == 80L * DIMS[ei]) {
            E[ei++] = (const float*)d_in[i];
        } else {
            L[li++] = (const float*)d_in[i];
        }
    }

    const float* Wd = (const float*)d_in[18];
    const float* bd = (const float*)d_in[19];

    // Phase B: field 2 (big, working set ~ L2 size)
    mean_kernel<50, 500000, 2><<<B_TOTAL / 4, 320>>>(x[2], E[2]);
    // Phase A: field 3 (table fully L2-resident: 32MB)
    mean_kernel<20, 100000, 3><<<B_TOTAL / 4, 320>>>(x[3], E[3]);
    // Phase C: cheap fields + L + epilogue
    final_kernel<<<B_TOTAL / 16, 256>>>(
        x[0], x[1], x[2], x[3], x[4], x[5],
        E[0], E[1], E[4], E[5],
        L[0], L[1], L[2], L[3], L[4], L[5],
        Wd, bd, (float*)d_out);
}

// round 6
// speedup vs baseline: 1.1051x; 1.0189x over previous
#include <cuda_runtime.h>
#include <math.h>

// FFM forward: B=16384, LATENT=16, F=6 fields.
// DIMS     = {1000000, 500000, 500000, 100000, 10000, 1000}
// SEQ_LENS = [1, 1, 50, 20, 1, 1]
//
// Round 5: token-range segmentation for E2. Two sequential passes, each
// touching only half the E2 table (64.5MB unique < 126MB L2), so the ~2x
// access multiplicity is actually captured by L2. Partial sums accumulate
// in a 5.2MB L2-resident scratch. Field 3 (table = 32MB, L2-resident) is
// fused into the final kernel along with the cheap fields and epilogue.

#define B_TOTAL 16384
#define LAT 16

__device__ float g_M2[(size_t)B_TOTAL * 5 * LAT];   // 5.24 MB scratch

// ---------------------------------------------------------------------------
// E2 segment pass: accumulate slot sums for tokens in [LO, HI).
// Thread = (slot, lane, elem); 320 threads = 16 lanes x 5 slots x 4 elems.
// FIRST pass writes raw sums; LAST pass adds, scales by 1/50, writes mean.
// ---------------------------------------------------------------------------
template<int LO, int HI, bool FIRST>
__global__ __launch_bounds__(320) void e2_seg_kernel(const int* __restrict__ x2,
                                                     const float* __restrict__ E2)
{
    constexpr int BPB = 4;
    __shared__ int tk[BPB][50];

    const int tid = threadIdx.x;
    const int b0  = blockIdx.x * BPB;

    for (int i = tid; i < BPB * 50; i += 320) {
        tk[i / 50][i % 50] = x2[(size_t)b0 * 50 + i];
    }
    __syncthreads();

    const int lane = tid & 15;
    const int sy   = (tid >> 4) % 5;
    const int z    = tid / 80;

    const float* base = E2 + (size_t)sy * 500000 * LAT + lane;

    float p[4] = {0.f, 0.f, 0.f, 0.f};
#pragma unroll
    for (int t = 0; t < 50; ++t) {
        const int tok = tk[z][t];
        if (tok >= LO && tok < HI)                 // uniform per 16-lane group
            p[t & 3] += __ldg(base + (size_t)tok * LAT);
    }
    const float s = (p[0] + p[1]) + (p[2] + p[3]);

    float* dst = &g_M2[((size_t)(b0 + z) * 5 + sy) * LAT + lane];
    if (FIRST) {
        *dst = s;                                   // raw partial sum
    } else {
        *dst = (*dst + s) * (1.0f / 50.0f);         // finish mean
    }
}

// ---------------------------------------------------------------------------
// Final kernel: field 3 (L2-resident table) + fields 0,1,4,5 + L gathers
// + fm/lin epilogue. 16 lanes per element, 256 threads = 16 elements.
// ---------------------------------------------------------------------------
__global__ __launch_bounds__(256) void final_kernel(
    const int* __restrict__ x0, const int* __restrict__ x1, const int* __restrict__ x2,
    const int* __restrict__ x3, const int* __restrict__ x4, const int* __restrict__ x5,
    const float* __restrict__ E0, const float* __restrict__ E1,
    const float* __restrict__ E3, const float* __restrict__ E4, const float* __restrict__ E5,
    const float* __restrict__ L0, const float* __restrict__ L1, const float* __restrict__ L2,
    const float* __restrict__ L3, const float* __restrict__ L4, const float* __restrict__ L5,
    const float* __restrict__ Wd, const float* __restrict__ bd,
    float* __restrict__ out)
{
    __shared__ int tk[16][74];   // [elem][f0|f1|f2*50|f3*20|f4|f5]

    const int tid = threadIdx.x;
    const int b0  = blockIdx.x * 16;

    for (int i = tid; i < 16 * 74; i += 256) {
        const int e = i / 74, o = i % 74;
        const int b = b0 + e;
        int v;
        if      (o == 0)  v = x0[b];
        else if (o == 1)  v = x1[b];
        else if (o < 52)  v = x2[(size_t)b * 50 + (o - 2)];
        else if (o < 72)  v = x3[(size_t)b * 20 + (o - 52)];
        else if (o == 72) v = x4[b];
        else              v = x5[b];
        tk[e][o] = v;
    }
    __syncthreads();

    const int lane = tid & 15;
    const int z    = tid >> 4;
    const int b    = b0 + z;

    const float w0 = __ldg(Wd + 0);
    const float w1 = __ldg(Wd + 1);
    const float w2 = __ldg(Wd + 2) * (1.0f / 50.0f);
    const float w3 = __ldg(Wd + 3) * (1.0f / 20.0f);
    const float w4 = __ldg(Wd + 4);
    const float w5 = __ldg(Wd + 5);

    // ---- field 3: 5-slot means, table L2-resident (32MB) ----
    float m3[5];
#pragma unroll
    for (int s = 0; s < 5; ++s) {
        const float* base = E3 + (size_t)s * 100000 * LAT + lane;
        float p0 = 0.f, p1 = 0.f, p2 = 0.f, p3 = 0.f;
#pragma unroll
        for (int t = 0; t < 20; t += 4) {
            p0 += __ldg(base + (size_t)tk[z][52 + t]     * LAT);
            p1 += __ldg(base + (size_t)tk[z][52 + t + 1] * LAT);
            p2 += __ldg(base + (size_t)tk[z][52 + t + 2] * LAT);
            p3 += __ldg(base + (size_t)tk[z][52 + t + 3] * LAT);
        }
        m3[s] = ((p0 + p1) + (p2 + p3)) * (1.0f / 20.0f);
    }

    // ---- single-token fields + m2 scratch ----
    const int t0 = tk[z][0], t1 = tk[z][1], t4 = tk[z][72], t5 = tk[z][73];
    float a0[5], a1[5], a4[5], a5[5], m2[5];
#pragma unroll
    for (int s = 0; s < 5; ++s) {
        a0[s] = __ldg(E0 + ((size_t)s * 1000000 + t0) * LAT + lane);
        a1[s] = __ldg(E1 + ((size_t)s *  500000 + t1) * LAT + lane);
        a4[s] = __ldg(E4 + ((size_t)s *   10000 + t4) * LAT + lane);
        a5[s] = __ldg(E5 + ((size_t)s *    1000 + t5) * LAT + lane);
        m2[s] = g_M2[((size_t)b * 5 + s) * LAT + lane];
    }

    // ---- linear term (L gathers once per 16-lane group; broadcast) ----
    float lp[4];
    lp[0] = __ldg(L0 + t0) * w0;
    lp[1] = __ldg(L1 + t1) * w1;
    lp[2] = __ldg(L4 + t4) * w4;
    lp[3] = __ldg(L5 + t5) * w5;
#pragma unroll
    for (int t = 0; t < 50; ++t) lp[t & 3] += __ldg(L2 + tk[z][2 + t]) * w2;
#pragma unroll
    for (int t = 0; t < 20; ++t) lp[t & 3] += __ldg(L3 + tk[z][52 + t]) * w3;
    const float lin = (lp[0] + lp[1]) + (lp[2] + lp[3]);

    // ---- fm = sum over pairs (i<j): a_i[slot j-1] * a_j[slot i] ----
    float fm = 0.f;
    fm += a0[0]*a1[0];   // (0,1)
    fm += a0[1]*m2[0];   // (0,2)
    fm += a0[2]*m3[0];   // (0,3)
    fm += a0[3]*a4[0];   // (0,4)
    fm += a0[4]*a5[0];   // (0,5)
    fm += a1[1]*m2[1];   // (1,2)
    fm += a1[2]*m3[1];   // (1,3)
    fm += a1[3]*a4[1];   // (1,4)
    fm += a1[4]*a5[1];   // (1,5)
    fm += m2[2]*m3[2];   // (2,3)
    fm += m2[3]*a4[2];   // (2,4)
    fm += m2[4]*a5[2];   // (2,5)
    fm += m3[3]*a4[3];   // (3,4)
    fm += m3[4]*a5[3];   // (3,5)
    fm += a4[4]*a5[4];   // (4,5)

    fm += __shfl_xor_sync(0xffffffffu, fm, 8, 16);
    fm += __shfl_xor_sync(0xffffffffu, fm, 4, 16);
    fm += __shfl_xor_sync(0xffffffffu, fm, 2, 16);
    fm += __shfl_xor_sync(0xffffffffu, fm, 1, 16);

    if (lane == 0) {
        float v = lin + __ldg(bd);
        v = v > 0.f ? v : 0.f;      // relu
        v += fm;
        out[b] = 1.0f / (1.0f + expf(-v));
    }
}

extern "C" void kernel_launch(void* const* d_in, const int* in_sizes, int n_in,
                              void* d_out, int out_size)
{
    static const long DIMS[6] = {1000000, 500000, 500000, 100000, 10000, 1000};

    const int*   x[6];
    const float* E[6];
    const float* L[6];

    for (int i = 0; i < 6; ++i) x[i] = (const int*)d_in[i];

    // Inputs 6..17 are E and L tables in field order; disambiguate by size:
    // E_i has 80*DIMS[i] elements, L_i has DIMS[i]. Disjoint sets.
    int ei = 0, li = 0;
    for (int i = 6; i < 18 && i < n_in; ++i) {
        long sz = (long)in_sizes[i];
        if (ei < 6 && sz == 80L * DIMS[ei]) {
            E[ei++] = (const float*)d_in[i];
        } else {
            L[li++] = (const float*)d_in[i];
        }
    }

    const float* Wd = (const float*)d_in[18];
    const float* bd = (const float*)d_in[19];

    // E2 in two token-range segments: each pass's working set (~64MB) fits
    // in L2, so the ~2x token multiplicity becomes L2 hits.
    e2_seg_kernel<0,      250000, true ><<<B_TOTAL / 4, 320>>>(x[2], E[2]);
    e2_seg_kernel<250000, 500000, false><<<B_TOTAL / 4, 320>>>(x[2], E[2]);

    // Field 3 (L2-resident table) + cheap fields + linear + epilogue.
    final_kernel<<<B_TOTAL / 16, 256>>>(
        x[0], x[1], x[2], x[3], x[4], x[5],
        E[0], E[1], E[3], E[4], E[5],
        L[0], L[1], L[2], L[3], L[4], L[5],
        Wd, bd, (float*)d_out);
}